// round 16
// baseline (speedup 1.0000x reference)
#include <cuda_runtime.h>
#include <cstdint>

#define NBODY      8192
#define BLOCK      128
#define IT         2                      // i-bodies per thread
#define IBLK       (BLOCK * IT)           // 256 i-bodies per block
#define NSPLIT     64
#define JCHUNK     (NBODY / NSPLIT)       // 128 j-bodies per block
#define NPAIRS     (JCHUNK / 2)           // 64 packed j-pairs
#define NQUADS     (NPAIRS / 2)           // 32 float4 groups (2 pairs each)
#define SOFT2      (0.01f * 0.01f)

__device__ __forceinline__ uint64_t f2_add(uint64_t a, uint64_t b) {
    uint64_t r; asm("add.rn.f32x2 %0, %1, %2;" : "=l"(r) : "l"(a), "l"(b)); return r;
}
__device__ __forceinline__ uint64_t f2_mul(uint64_t a, uint64_t b) {
    uint64_t r; asm("mul.rn.f32x2 %0, %1, %2;" : "=l"(r) : "l"(a), "l"(b)); return r;
}
__device__ __forceinline__ uint64_t f2_fma(uint64_t a, uint64_t b, uint64_t c) {
    uint64_t r; asm("fma.rn.f32x2 %0, %1, %2, %3;" : "=l"(r) : "l"(a), "l"(b), "l"(c)); return r;
}
__device__ __forceinline__ uint64_t f2_pack(float lo, float hi) {
    uint64_t r; asm("mov.b64 %0, {%1, %2};" : "=l"(r) : "f"(lo), "f"(hi)); return r;
}
__device__ __forceinline__ uint64_t f2_bcast(float v) {
    uint64_t r; asm("mov.b64 %0, {%1, %1};" : "=l"(r) : "f"(v)); return r;
}
__device__ __forceinline__ void f2_unpack(float& lo, float& hi, uint64_t v) {
    asm("mov.b64 {%0, %1}, %2;" : "=f"(lo), "=f"(hi) : "l"(v));
}

// Final probe: champion body (unroll 4), cap 7 -> reg budget 73 (trim 80->73),
// resident blocks 6->7 per SM (occ ~31% -> ~36%).
__global__ __launch_bounds__(BLOCK, 7)
void nbody_kernel(const float* __restrict__ pos,
                  const float* __restrict__ mass,
                  float* __restrict__ out) {
    const int tid = threadIdx.x;
    const int i0  = blockIdx.x * IBLK + tid;
    const int i1  = i0 + BLOCK;

    __shared__ float2 shx[NPAIRS];
    __shared__ float2 shy[NPAIRS];
    __shared__ float2 shz[NPAIRS];
    __shared__ float2 shm[NPAIRS];

    if (tid < NPAIRS) {
        const int j = blockIdx.y * JCHUNK + 2 * tid;
        shx[tid] = make_float2(pos[3 * j + 0], pos[3 * j + 3]);
        shy[tid] = make_float2(pos[3 * j + 1], pos[3 * j + 4]);
        shz[tid] = make_float2(pos[3 * j + 2], pos[3 * j + 5]);
        shm[tid] = make_float2(mass[j], mass[j + 1]);
    }

    const uint64_t nx0 = f2_bcast(-pos[3 * i0 + 0]);
    const uint64_t ny0 = f2_bcast(-pos[3 * i0 + 1]);
    const uint64_t nz0 = f2_bcast(-pos[3 * i0 + 2]);
    const uint64_t nx1 = f2_bcast(-pos[3 * i1 + 0]);
    const uint64_t ny1 = f2_bcast(-pos[3 * i1 + 1]);
    const uint64_t nz1 = f2_bcast(-pos[3 * i1 + 2]);
    const uint64_t s2p = f2_bcast(SOFT2);

    __syncthreads();

    uint64_t ax0 = 0ull, ay0 = 0ull, az0 = 0ull;
    uint64_t ax1 = 0ull, ay1 = 0ull, az1 = 0ull;

    const float4* __restrict__ qx = reinterpret_cast<const float4*>(shx);
    const float4* __restrict__ qy = reinterpret_cast<const float4*>(shy);
    const float4* __restrict__ qz = reinterpret_cast<const float4*>(shz);
    const float4* __restrict__ qm = reinterpret_cast<const float4*>(shm);

    #pragma unroll 4
    for (int k = 0; k < NQUADS; k++) {
        const float4 x4 = qx[k];
        const float4 y4 = qy[k];
        const float4 z4 = qz[k];
        const float4 m4 = qm[k];

        #pragma unroll
        for (int h = 0; h < 2; h++) {
            const uint64_t xp = (h == 0) ? f2_pack(x4.x, x4.y) : f2_pack(x4.z, x4.w);
            const uint64_t yp = (h == 0) ? f2_pack(y4.x, y4.y) : f2_pack(y4.z, y4.w);
            const uint64_t zp = (h == 0) ? f2_pack(z4.x, z4.y) : f2_pack(z4.z, z4.w);
            const uint64_t mp = (h == 0) ? f2_pack(m4.x, m4.y) : f2_pack(m4.z, m4.w);

            // ---- chain 0 (i0 vs j-pair) ----
            const uint64_t dx0 = f2_add(xp, nx0);
            const uint64_t dy0 = f2_add(yp, ny0);
            const uint64_t dz0 = f2_add(zp, nz0);
            uint64_t d20 = s2p;
            d20 = f2_fma(dx0, dx0, d20);
            d20 = f2_fma(dy0, dy0, d20);
            d20 = f2_fma(dz0, dz0, d20);

            // ---- chain 1 (i1 vs j-pair) ----
            const uint64_t dx1 = f2_add(xp, nx1);
            const uint64_t dy1 = f2_add(yp, ny1);
            const uint64_t dz1 = f2_add(zp, nz1);
            uint64_t d21 = s2p;
            d21 = f2_fma(dx1, dx1, d21);
            d21 = f2_fma(dy1, dy1, d21);
            d21 = f2_fma(dz1, dz1, d21);

            float a0, b0, a1, b1;
            f2_unpack(a0, b0, d20);
            f2_unpack(a1, b1, d21);
            const uint64_t inv0 = f2_pack(rsqrtf(a0), rsqrtf(b0));
            const uint64_t inv1 = f2_pack(rsqrtf(a1), rsqrtf(b1));

            const uint64_t w0 = f2_mul(mp, f2_mul(f2_mul(inv0, inv0), inv0));
            ax0 = f2_fma(w0, dx0, ax0);
            ay0 = f2_fma(w0, dy0, ay0);
            az0 = f2_fma(w0, dz0, az0);

            const uint64_t w1 = f2_mul(mp, f2_mul(f2_mul(inv1, inv1), inv1));
            ax1 = f2_fma(w1, dx1, ax1);
            ay1 = f2_fma(w1, dy1, ay1);
            az1 = f2_fma(w1, dz1, az1);
        }
    }

    float lo, hi;
    f2_unpack(lo, hi, ax0); atomicAdd(&out[3 * i0 + 0], lo + hi);
    f2_unpack(lo, hi, ay0); atomicAdd(&out[3 * i0 + 1], lo + hi);
    f2_unpack(lo, hi, az0); atomicAdd(&out[3 * i0 + 2], lo + hi);
    f2_unpack(lo, hi, ax1); atomicAdd(&out[3 * i1 + 0], lo + hi);
    f2_unpack(lo, hi, ay1); atomicAdd(&out[3 * i1 + 1], lo + hi);
    f2_unpack(lo, hi, az1); atomicAdd(&out[3 * i1 + 2], lo + hi);
}

extern "C" void kernel_launch(void* const* d_in, const int* in_sizes, int n_in,
                              void* d_out, int out_size) {
    const float* pos  = (const float*)d_in[0];   // (8192, 3) float32
    const float* mass = (const float*)d_in[1];   // (8192,)   float32
    float* out        = (float*)d_out;           // (8192, 3) float32

    // Graph-capturable async memset node (cheaper than a zeroing kernel launch)
    cudaMemsetAsync(out, 0, (size_t)NBODY * 3 * sizeof(float));

    dim3 grid(NBODY / IBLK, NSPLIT);              // 32 x 64 = 2048 blocks
    nbody_kernel<<<grid, BLOCK>>>(pos, mass, out);
}

// round 17
// speedup vs baseline: 1.0489x; 1.0489x over previous
#include <cuda_runtime.h>
#include <cstdint>

#define NBODY      8192
#define BLOCK      128
#define IT         2                      // i-bodies per thread
#define IBLK       (BLOCK * IT)           // 256 i-bodies per block
#define NSPLIT     64
#define JCHUNK     (NBODY / NSPLIT)       // 128 j-bodies per block
#define NPAIRS     (JCHUNK / 2)           // 64 packed j-pairs
#define NQUADS     (NPAIRS / 2)           // 32 float4 groups (2 pairs each)
#define SOFT2      (0.01f * 0.01f)

__device__ __forceinline__ uint64_t f2_add(uint64_t a, uint64_t b) {
    uint64_t r; asm("add.rn.f32x2 %0, %1, %2;" : "=l"(r) : "l"(a), "l"(b)); return r;
}
__device__ __forceinline__ uint64_t f2_mul(uint64_t a, uint64_t b) {
    uint64_t r; asm("mul.rn.f32x2 %0, %1, %2;" : "=l"(r) : "l"(a), "l"(b)); return r;
}
__device__ __forceinline__ uint64_t f2_fma(uint64_t a, uint64_t b, uint64_t c) {
    uint64_t r; asm("fma.rn.f32x2 %0, %1, %2, %3;" : "=l"(r) : "l"(a), "l"(b), "l"(c)); return r;
}
__device__ __forceinline__ uint64_t f2_pack(float lo, float hi) {
    uint64_t r; asm("mov.b64 %0, {%1, %2};" : "=l"(r) : "f"(lo), "f"(hi)); return r;
}
__device__ __forceinline__ uint64_t f2_bcast(float v) {
    uint64_t r; asm("mov.b64 %0, {%1, %1};" : "=l"(r) : "f"(v)); return r;
}
__device__ __forceinline__ void f2_unpack(float& lo, float& hi, uint64_t v) {
    asm("mov.b64 {%0, %1}, %2;" : "=f"(lo), "=f"(hi) : "l"(v));
}

// CHAMPION (R10, reproduced R13/R15): IT=2 packed-f32x2 chains, float4 quad
// tile reads, unroll 4, __launch_bounds__(128,6) -> 85-reg budget (80 used,
// no trim), memset node + atomic epilogue.
// Certified optimum of the (unroll x cap) lattice:
//   u2/c7=35.8  u4/c6=35.4-35.6(x3)  u4/c7=36.3  u8/c6=36.0  u8/c5=35.8
// fma busy = 23.3us = exact f32x2 rt=2 floor; total 37.7-37.9us.
__global__ __launch_bounds__(BLOCK, 6)
void nbody_kernel(const float* __restrict__ pos,
                  const float* __restrict__ mass,
                  float* __restrict__ out) {
    const int tid = threadIdx.x;
    const int i0  = blockIdx.x * IBLK + tid;
    const int i1  = i0 + BLOCK;

    __shared__ float2 shx[NPAIRS];
    __shared__ float2 shy[NPAIRS];
    __shared__ float2 shz[NPAIRS];
    __shared__ float2 shm[NPAIRS];

    if (tid < NPAIRS) {
        const int j = blockIdx.y * JCHUNK + 2 * tid;
        shx[tid] = make_float2(pos[3 * j + 0], pos[3 * j + 3]);
        shy[tid] = make_float2(pos[3 * j + 1], pos[3 * j + 4]);
        shz[tid] = make_float2(pos[3 * j + 2], pos[3 * j + 5]);
        shm[tid] = make_float2(mass[j], mass[j + 1]);
    }

    const uint64_t nx0 = f2_bcast(-pos[3 * i0 + 0]);
    const uint64_t ny0 = f2_bcast(-pos[3 * i0 + 1]);
    const uint64_t nz0 = f2_bcast(-pos[3 * i0 + 2]);
    const uint64_t nx1 = f2_bcast(-pos[3 * i1 + 0]);
    const uint64_t ny1 = f2_bcast(-pos[3 * i1 + 1]);
    const uint64_t nz1 = f2_bcast(-pos[3 * i1 + 2]);
    const uint64_t s2p = f2_bcast(SOFT2);

    __syncthreads();

    uint64_t ax0 = 0ull, ay0 = 0ull, az0 = 0ull;
    uint64_t ax1 = 0ull, ay1 = 0ull, az1 = 0ull;

    const float4* __restrict__ qx = reinterpret_cast<const float4*>(shx);
    const float4* __restrict__ qy = reinterpret_cast<const float4*>(shy);
    const float4* __restrict__ qz = reinterpret_cast<const float4*>(shz);
    const float4* __restrict__ qm = reinterpret_cast<const float4*>(shm);

    #pragma unroll 4
    for (int k = 0; k < NQUADS; k++) {
        const float4 x4 = qx[k];
        const float4 y4 = qy[k];
        const float4 z4 = qz[k];
        const float4 m4 = qm[k];

        #pragma unroll
        for (int h = 0; h < 2; h++) {
            const uint64_t xp = (h == 0) ? f2_pack(x4.x, x4.y) : f2_pack(x4.z, x4.w);
            const uint64_t yp = (h == 0) ? f2_pack(y4.x, y4.y) : f2_pack(y4.z, y4.w);
            const uint64_t zp = (h == 0) ? f2_pack(z4.x, z4.y) : f2_pack(z4.z, z4.w);
            const uint64_t mp = (h == 0) ? f2_pack(m4.x, m4.y) : f2_pack(m4.z, m4.w);

            // ---- chain 0 (i0 vs j-pair) ----
            const uint64_t dx0 = f2_add(xp, nx0);
            const uint64_t dy0 = f2_add(yp, ny0);
            const uint64_t dz0 = f2_add(zp, nz0);
            uint64_t d20 = s2p;
            d20 = f2_fma(dx0, dx0, d20);
            d20 = f2_fma(dy0, dy0, d20);
            d20 = f2_fma(dz0, dz0, d20);

            // ---- chain 1 (i1 vs j-pair) ----
            const uint64_t dx1 = f2_add(xp, nx1);
            const uint64_t dy1 = f2_add(yp, ny1);
            const uint64_t dz1 = f2_add(zp, nz1);
            uint64_t d21 = s2p;
            d21 = f2_fma(dx1, dx1, d21);
            d21 = f2_fma(dy1, dy1, d21);
            d21 = f2_fma(dz1, dz1, d21);

            float a0, b0, a1, b1;
            f2_unpack(a0, b0, d20);
            f2_unpack(a1, b1, d21);
            const uint64_t inv0 = f2_pack(rsqrtf(a0), rsqrtf(b0));
            const uint64_t inv1 = f2_pack(rsqrtf(a1), rsqrtf(b1));

            const uint64_t w0 = f2_mul(mp, f2_mul(f2_mul(inv0, inv0), inv0));
            ax0 = f2_fma(w0, dx0, ax0);
            ay0 = f2_fma(w0, dy0, ay0);
            az0 = f2_fma(w0, dz0, az0);

            const uint64_t w1 = f2_mul(mp, f2_mul(f2_mul(inv1, inv1), inv1));
            ax1 = f2_fma(w1, dx1, ax1);
            ay1 = f2_fma(w1, dy1, ay1);
            az1 = f2_fma(w1, dz1, az1);
        }
    }

    float lo, hi;
    f2_unpack(lo, hi, ax0); atomicAdd(&out[3 * i0 + 0], lo + hi);
    f2_unpack(lo, hi, ay0); atomicAdd(&out[3 * i0 + 1], lo + hi);
    f2_unpack(lo, hi, az0); atomicAdd(&out[3 * i0 + 2], lo + hi);
    f2_unpack(lo, hi, ax1); atomicAdd(&out[3 * i1 + 0], lo + hi);
    f2_unpack(lo, hi, ay1); atomicAdd(&out[3 * i1 + 1], lo + hi);
    f2_unpack(lo, hi, az1); atomicAdd(&out[3 * i1 + 2], lo + hi);
}

extern "C" void kernel_launch(void* const* d_in, const int* in_sizes, int n_in,
                              void* d_out, int out_size) {
    const float* pos  = (const float*)d_in[0];   // (8192, 3) float32
    const float* mass = (const float*)d_in[1];   // (8192,)   float32
    float* out        = (float*)d_out;           // (8192, 3) float32

    // Graph-capturable async memset node (cheaper than a zeroing kernel launch)
    cudaMemsetAsync(out, 0, (size_t)NBODY * 3 * sizeof(float));

    dim3 grid(NBODY / IBLK, NSPLIT);              // 32 x 64 = 2048 blocks
    nbody_kernel<<<grid, BLOCK>>>(pos, mass, out);
}